// round 5
// baseline (speedup 1.0000x reference)
#include <cuda_runtime.h>
#include <cstdint>
#include <cstddef>

#define TT 511          // T-1 rows
#define VV 32000
#define EE 512
#define HH 512
#define SPLITS 25
#define KCHUNK 1280     // 32000 / 25, multiple of 16

// ---------------- scratch (__device__ globals; no allocation) ----------------
__device__ float g_part[SPLITS * 512 * 512];          // split-K partials for emb
__device__ float g_emb[TT * EE];
__device__ float g_xproj[TT * HH];
__device__ float g_hs[TT * HH];
__device__ float g_logits[(size_t)TT * VV];

// ---------------- f32x2 helpers ----------------
__device__ __forceinline__ void fma2(unsigned long long& d, unsigned long long a,
                                     unsigned long long b) {
    asm("fma.rn.f32x2 %0, %1, %2, %0;" : "+l"(d) : "l"(a), "l"(b));
}
__device__ __forceinline__ unsigned long long dup2(float x) {
    unsigned long long d;
    asm("mov.b64 %0, {%1, %1};" : "=l"(d) : "f"(x));
    return d;
}
__device__ __forceinline__ float2 unpack2(unsigned long long d) {
    float2 r;
    asm("mov.b64 {%0, %1}, %2;" : "=f"(r.x), "=f"(r.y) : "l"(d));
    return r;
}

// ---------------- 128x128 NT fp32 GEMM (C = A[M,K] * B[N,K]^T), split-K via z ----
// (R1 version verbatim)
__global__ void __launch_bounds__(256, 1)
gemm_nt128(const float* __restrict__ A, int lda,
           const float* __restrict__ B, int ldb,
           float* __restrict__ C, int ldc, size_t zStride,
           int M, int kLen)
{
    __shared__ float As[16][132];
    __shared__ float Bs[16][132];
    const int tid = threadIdx.x;
    const int nt = blockIdx.x, mt = blockIdx.y, sz = blockIdx.z;
    const int kOff = sz * kLen;
    float* Cz = C + (size_t)sz * zStride;
    const int ty = tid >> 4, tx = tid & 15;
    const int m0 = ty * 8, n0 = tx * 8;

    unsigned long long acc[8][4];
#pragma unroll
    for (int i = 0; i < 8; i++)
#pragma unroll
        for (int j = 0; j < 4; j++) acc[i][j] = 0ull;

    for (int kb = 0; kb < kLen; kb += 16) {
#pragma unroll
        for (int i = 0; i < 2; i++) {
            int idx = tid + i * 256;
            int m = idx >> 2;
            int k4 = (idx & 3) << 2;
            size_t gk = (size_t)(kOff + kb + k4);
            float4 va = make_float4(0.f, 0.f, 0.f, 0.f);
            int ra = mt * 128 + m;
            if (ra < M) va = *(const float4*)(A + (size_t)ra * lda + gk);
            As[k4 + 0][m] = va.x; As[k4 + 1][m] = va.y;
            As[k4 + 2][m] = va.z; As[k4 + 3][m] = va.w;
            int rb = nt * 128 + m;
            float4 vb = *(const float4*)(B + (size_t)rb * ldb + gk);
            Bs[k4 + 0][m] = vb.x; Bs[k4 + 1][m] = vb.y;
            Bs[k4 + 2][m] = vb.z; Bs[k4 + 3][m] = vb.w;
        }
        __syncthreads();
#pragma unroll
        for (int k = 0; k < 16; k++) {
            float4 a0 = *(const float4*)&As[k][m0];
            float4 a1 = *(const float4*)&As[k][m0 + 4];
            ulonglong2 b0 = *(const ulonglong2*)&Bs[k][n0];
            ulonglong2 b1 = *(const ulonglong2*)&Bs[k][n0 + 4];
            float av[8] = {a0.x, a0.y, a0.z, a0.w, a1.x, a1.y, a1.z, a1.w};
#pragma unroll
            for (int i = 0; i < 8; i++) {
                unsigned long long ad = dup2(av[i]);
                fma2(acc[i][0], ad, b0.x);
                fma2(acc[i][1], ad, b0.y);
                fma2(acc[i][2], ad, b1.x);
                fma2(acc[i][3], ad, b1.y);
            }
        }
        __syncthreads();
    }
#pragma unroll
    for (int i = 0; i < 8; i++) {
        int r = mt * 128 + m0 + i;
        if (r >= M) continue;
        float* cp = Cz + (size_t)r * ldc + nt * 128 + n0;
#pragma unroll
        for (int j = 0; j < 4; j++) {
            float2 v = unpack2(acc[i][j]);
            cp[2 * j] = v.x;
            cp[2 * j + 1] = v.y;
        }
    }
}

// ---------------- reduce split-K partials into emb ----------------
__global__ void reduce_emb_kernel()
{
    int i = blockIdx.x * 256 + threadIdx.x;
    if (i >= TT * EE) return;
    float s = 0.f;
#pragma unroll
    for (int p = 0; p < SPLITS; p++) s += g_part[p * (512 * 512) + i];
    g_emb[i] = s;
}

// ---------------- xproj = emb @ W_x^T + b  (64x64 tiles, K=512) ----------------
__global__ void __launch_bounds__(256)
xproj_kernel(const float* __restrict__ W_x, const float* __restrict__ bias)
{
    __shared__ float As[16][68];
    __shared__ float Bs[16][68];
    const int tid = threadIdx.x;
    const int nt = blockIdx.x, mt = blockIdx.y;
    const int ty = tid >> 4, tx = tid & 15;
    const int m0 = ty * 4, n0 = tx * 4;
    float acc[4][4] = {};

    for (int kb = 0; kb < 512; kb += 16) {
        int m = tid >> 2, k4 = (tid & 3) << 2;
        float4 va = make_float4(0.f, 0.f, 0.f, 0.f);
        int ra = mt * 64 + m;
        if (ra < TT) va = *(const float4*)(g_emb + (size_t)ra * 512 + kb + k4);
        As[k4 + 0][m] = va.x; As[k4 + 1][m] = va.y;
        As[k4 + 2][m] = va.z; As[k4 + 3][m] = va.w;
        float4 vb = *(const float4*)(W_x + (size_t)(nt * 64 + m) * 512 + kb + k4);
        Bs[k4 + 0][m] = vb.x; Bs[k4 + 1][m] = vb.y;
        Bs[k4 + 2][m] = vb.z; Bs[k4 + 3][m] = vb.w;
        __syncthreads();
#pragma unroll
        for (int k = 0; k < 16; k++) {
            float4 a = *(const float4*)&As[k][m0];
            float4 b = *(const float4*)&Bs[k][n0];
            float aa[4] = {a.x, a.y, a.z, a.w};
            float bb[4] = {b.x, b.y, b.z, b.w};
#pragma unroll
            for (int i = 0; i < 4; i++)
#pragma unroll
                for (int j = 0; j < 4; j++) acc[i][j] += aa[i] * bb[j];
        }
        __syncthreads();
    }
#pragma unroll
    for (int i = 0; i < 4; i++) {
        int r = mt * 64 + m0 + i;
        if (r >= TT) continue;
#pragma unroll
        for (int j = 0; j < 4; j++) {
            int col = nt * 64 + n0 + j;
            g_xproj[(size_t)r * 512 + col] = acc[i][j] + bias[col];
        }
    }
}

// ---------------- Elman recurrence: warp-local, 1 cluster barrier per step ----
// 8 CTAs x 1024 threads. Warp w owns rows {c*64+2w, +1}. Lane l owns
// k in {4l+128i : i=0..3} (16 k per row; LDS.128 of h is fully coalesced).
// Reduce: one hi/lo exchange + 4 xor-butterflies (both rows in one tree).
// The 8 remote h-stores are spread across lanes 0..7 / 16..23 (one each).
// No __syncthreads in the step loop; one barrier.cluster per step.
__global__ void __cluster_dims__(8, 1, 1) __launch_bounds__(1024, 1)
rnn_kernel(const float* __restrict__ W_h)
{
    extern __shared__ float sm[];
    float* xps  = sm;                        // [TT*64]
    float* hbuf = sm + TT * 64;              // [2][512]

    const int tid = threadIdx.x;
    const int w = tid >> 5, l = tid & 31;
    const int hi = (l >> 4) & 1;             // which of the warp's 2 rows I help
    const int li = l & 15;
    const int c = (int)blockIdx.x;
    const int row0 = c * 64 + 2 * w;         // warp's first row (global)
    const int kb = 4 * l;                    // lane's base k (plus 128*i)

    // weights: rows row0, row0+1 at k = kb + 128*i, 4 floats each -> ulonglong2
    ulonglong2 wv0[4], wv1[4];
#pragma unroll
    for (int i = 0; i < 4; i++) {
        wv0[i] = *(const ulonglong2*)(W_h + (size_t)row0 * 512 + kb + 128 * i);
        wv1[i] = *(const ulonglong2*)(W_h + (size_t)(row0 + 1) * 512 + kb + 128 * i);
    }

    // preload this CTA's xproj slice
    for (int i = tid; i < TT * 64; i += 1024)
        xps[i] = g_xproj[(size_t)(i >> 6) * 512 + c * 64 + (i & 63)];
    if (tid < 1024) { if (tid < 512) hbuf[tid] = 0.f; else hbuf[tid] = 0.f; }

    // my single peer destination (lanes with li<8 store row hi to CTA li)
    uint32_t hlocal = (uint32_t)__cvta_generic_to_shared(hbuf);
    uint32_t mypeer;
    asm("mapa.shared::cluster.u32 %0, %1, %2;" : "=r"(mypeer) : "r"(hlocal), "r"(li & 7));

    __syncthreads();
    asm volatile("barrier.cluster.arrive.aligned;" ::: "memory");
    asm volatile("barrier.cluster.wait.aligned;" ::: "memory");

    for (int t = 0; t < TT; t++) {
        const int b = t & 1;
        const float* hb = hbuf + b * 512 + kb;

        unsigned long long a00 = 0ull, a01 = 0ull, a10 = 0ull, a11 = 0ull;
#pragma unroll
        for (int i = 0; i < 4; i++) {
            ulonglong2 hv = *(const ulonglong2*)(hb + 128 * i);   // coalesced LDS.128
            fma2(a00, wv0[i].x, hv.x);
            fma2(a01, wv0[i].y, hv.y);
            fma2(a10, wv1[i].x, hv.x);
            fma2(a11, wv1[i].y, hv.y);
        }
        float2 f0 = unpack2(a00), f1 = unpack2(a01);
        float2 f2 = unpack2(a10), f3 = unpack2(a11);
        float s0 = (f0.x + f0.y) + (f1.x + f1.y);   // partial for row0
        float s1 = (f2.x + f2.y) + (f3.x + f3.y);   // partial for row1

        // exchange: low half keeps row0, high half keeps row1
        float send = hi ? s0 : s1;
        float keep = hi ? s1 : s0;
        float v = keep + __shfl_xor_sync(0xffffffffu, send, 16);
        v += __shfl_xor_sync(0xffffffffu, v, 8);
        v += __shfl_xor_sync(0xffffffffu, v, 4);
        v += __shfl_xor_sync(0xffffffffu, v, 2);
        v += __shfl_xor_sync(0xffffffffu, v, 1);
        // now all 16 lanes of each half hold their row's full dot product

        float x = xps[t * 64 + 2 * w + hi];
        float h = 1.f / (1.f + __expf(-(x + v)));

        if (li < 8) {
            uint32_t hoff = (uint32_t)((((b ^ 1) * 512) + row0 + hi) * 4);
            asm volatile("st.shared::cluster.f32 [%0], %1;"
                         :: "r"(mypeer + hoff), "f"(h) : "memory");
        }
        if (li == 0)
            g_hs[(size_t)t * 512 + row0 + hi] = h;

        asm volatile("barrier.cluster.arrive.aligned;" ::: "memory");
        asm volatile("barrier.cluster.wait.aligned;" ::: "memory");
    }
}

// ---------------- row softmax over V=32000 ----------------
__global__ void __launch_bounds__(256)
softmax_kernel(float* __restrict__ out)
{
    const int t = blockIdx.x;
    const int tid = threadIdx.x;
    const float4* r4 = (const float4*)(g_logits + (size_t)t * VV);
    float4* o4 = (float4*)(out + (size_t)t * VV);
    __shared__ float red[256];

    float mx = -3.402823466e38f;
    for (int i = tid; i < VV / 4; i += 256) {
        float4 v = r4[i];
        mx = fmaxf(mx, fmaxf(fmaxf(v.x, v.y), fmaxf(v.z, v.w)));
    }
    red[tid] = mx; __syncthreads();
    for (int o = 128; o > 0; o >>= 1) {
        if (tid < o) red[tid] = fmaxf(red[tid], red[tid + o]);
        __syncthreads();
    }
    mx = red[0]; __syncthreads();

    float sum = 0.f;
    for (int i = tid; i < VV / 4; i += 256) {
        float4 v = r4[i];
        v.x = __expf(v.x - mx); v.y = __expf(v.y - mx);
        v.z = __expf(v.z - mx); v.w = __expf(v.w - mx);
        o4[i] = v;
        sum += (v.x + v.y) + (v.z + v.w);
    }
    red[tid] = sum; __syncthreads();
    for (int o = 128; o > 0; o >>= 1) {
        if (tid < o) red[tid] += red[tid + o];
        __syncthreads();
    }
    float inv = 1.f / red[0];

    for (int i = tid; i < VV / 4; i += 256) {
        float4 v = o4[i];
        v.x *= inv; v.y *= inv; v.z *= inv; v.w *= inv;
        o4[i] = v;
    }
}

// ---------------- launch ----------------
extern "C" void kernel_launch(void* const* d_in, const int* in_sizes, int n_in,
                              void* d_out, int out_size)
{
    const float* sent = (const float*)d_in[0];
    const float* W_e  = (const float*)d_in[1];
    const float* W_x  = (const float*)d_in[2];
    const float* W_h  = (const float*)d_in[3];
    const float* W_p  = (const float*)d_in[4];
    const float* b    = (const float*)d_in[5];
    float* out = (float*)d_out;

    float *part, *hs_ptr, *logits;
    cudaGetSymbolAddress((void**)&part,   g_part);
    cudaGetSymbolAddress((void**)&hs_ptr, g_hs);
    cudaGetSymbolAddress((void**)&logits, g_logits);

    // rnn dynamic smem: xps (TT*64) + hbuf (2*512)
    const int rnnSmem = (TT * 64 + 1024) * (int)sizeof(float);
    cudaFuncSetAttribute(rnn_kernel,
                         cudaFuncAttributeMaxDynamicSharedMemorySize, rnnSmem);

    // emb partials: sent[0:511] (511x32000) @ W_e^T (32000x512), split-K=25
    gemm_nt128<<<dim3(4, 4, SPLITS), 256>>>(sent, VV, W_e, VV,
                                            part, 512, (size_t)512 * 512, TT, KCHUNK);
    reduce_emb_kernel<<<(TT * EE + 255) / 256, 256>>>();
    // xproj = emb @ W_x^T + b
    xproj_kernel<<<dim3(8, 8), 256>>>(W_x, b);
    // sequential Elman scan (single 8-CTA cluster)
    rnn_kernel<<<8, 1024, rnnSmem>>>(W_h);
    // logits = hs @ W_p^T
    gemm_nt128<<<dim3(250, 4, 1), 256>>>(hs_ptr, 512, W_p, 512,
                                         logits, VV, 0, TT, 512);
    // preds = softmax(logits)
    softmax_kernel<<<TT, 256>>>(out);
}

// round 6
// speedup vs baseline: 1.8922x; 1.8922x over previous
#include <cuda_runtime.h>
#include <cstdint>
#include <cstddef>

#define TT 511          // T-1 rows
#define VV 32000
#define EE 512
#define HH 512
#define SPLITS 25
#define KCHUNK 1280     // 32000 / 25, multiple of 16

// ---------------- scratch (__device__ globals; no allocation) ----------------
__device__ float g_part[SPLITS * 512 * 512];          // split-K partials for emb
__device__ float g_emb[TT * EE];
__device__ float g_xproj[TT * HH];
__device__ float g_hs[TT * HH];
__device__ float g_logits[(size_t)TT * VV];

// ---------------- f32x2 helpers ----------------
__device__ __forceinline__ void fma2(unsigned long long& d, unsigned long long a,
                                     unsigned long long b) {
    asm("fma.rn.f32x2 %0, %1, %2, %0;" : "+l"(d) : "l"(a), "l"(b));
}
__device__ __forceinline__ unsigned long long dup2(float x) {
    unsigned long long d;
    asm("mov.b64 %0, {%1, %1};" : "=l"(d) : "f"(x));
    return d;
}
__device__ __forceinline__ float2 unpack2(unsigned long long d) {
    float2 r;
    asm("mov.b64 {%0, %1}, %2;" : "=f"(r.x), "=f"(r.y) : "l"(d));
    return r;
}

// ---------------- 128x128 NT fp32 GEMM (C = A[M,K] * B[N,K]^T), split-K via z ----
// Double-buffered SMEM, ONE __syncthreads per k-tile, occupancy 2.
// iter i: compute(buf cur) reads cur; STS writes cur^1; barrier at end orders
// everything: no thread enters iter i+1 (whose STS overwrites cur) until all
// threads finished reading cur in iter i.
__global__ void __launch_bounds__(256, 2)
gemm_nt128(const float* __restrict__ A, int lda,
           const float* __restrict__ B, int ldb,
           float* __restrict__ C, int ldc, size_t zStride,
           int M, int kLen)
{
    __shared__ float As[2][16][132];
    __shared__ float Bs[2][16][132];
    const int tid = threadIdx.x;
    const int nt = blockIdx.x, mt = blockIdx.y, sz = blockIdx.z;
    const int kOff = sz * kLen;
    float* Cz = C + (size_t)sz * zStride;
    const int ty = tid >> 4, tx = tid & 15;
    const int m0 = ty * 8, n0 = tx * 8;

    // per-thread load geometry (fixed across k-tiles)
    int lm[2], lk4[2], ra[2], rb[2];
    bool aok[2];
#pragma unroll
    for (int i = 0; i < 2; i++) {
        int idx = tid + i * 256;
        lm[i] = idx >> 2;
        lk4[i] = (idx & 3) << 2;
        ra[i] = mt * 128 + lm[i];
        rb[i] = nt * 128 + lm[i];
        aok[i] = (ra[i] < M);
    }

    unsigned long long acc[8][4];
#pragma unroll
    for (int i = 0; i < 8; i++)
#pragma unroll
        for (int j = 0; j < 4; j++) acc[i][j] = 0ull;

    // prologue: tile 0 straight to buf 0
#pragma unroll
    for (int i = 0; i < 2; i++) {
        size_t gk = (size_t)(kOff + lk4[i]);
        float4 va = aok[i] ? *(const float4*)(A + (size_t)ra[i] * lda + gk)
                           : make_float4(0.f, 0.f, 0.f, 0.f);
        float4 vb = *(const float4*)(B + (size_t)rb[i] * ldb + gk);
        int m = lm[i], k4 = lk4[i];
        As[0][k4 + 0][m] = va.x; As[0][k4 + 1][m] = va.y;
        As[0][k4 + 2][m] = va.z; As[0][k4 + 3][m] = va.w;
        Bs[0][k4 + 0][m] = vb.x; Bs[0][k4 + 1][m] = vb.y;
        Bs[0][k4 + 2][m] = vb.z; Bs[0][k4 + 3][m] = vb.w;
    }
    __syncthreads();

    int cur = 0;
    for (int kb = 0; kb < kLen; kb += 16) {
        const bool has_next = (kb + 16 < kLen);
        float4 pa[2], pb[2];
        if (has_next) {
#pragma unroll
            for (int i = 0; i < 2; i++) {
                size_t gk = (size_t)(kOff + kb + 16 + lk4[i]);
                pa[i] = aok[i] ? *(const float4*)(A + (size_t)ra[i] * lda + gk)
                               : make_float4(0.f, 0.f, 0.f, 0.f);
                pb[i] = *(const float4*)(B + (size_t)rb[i] * ldb + gk);
            }
        }

#pragma unroll
        for (int k = 0; k < 16; k++) {
            float4 a0 = *(const float4*)&As[cur][k][m0];
            float4 a1 = *(const float4*)&As[cur][k][m0 + 4];
            ulonglong2 b0 = *(const ulonglong2*)&Bs[cur][k][n0];
            ulonglong2 b1 = *(const ulonglong2*)&Bs[cur][k][n0 + 4];
            float av[8] = {a0.x, a0.y, a0.z, a0.w, a1.x, a1.y, a1.z, a1.w};
#pragma unroll
            for (int i = 0; i < 8; i++) {
                unsigned long long ad = dup2(av[i]);
                fma2(acc[i][0], ad, b0.x);
                fma2(acc[i][1], ad, b0.y);
                fma2(acc[i][2], ad, b1.x);
                fma2(acc[i][3], ad, b1.y);
            }
        }

        if (has_next) {
            int nb = cur ^ 1;
#pragma unroll
            for (int i = 0; i < 2; i++) {
                int m = lm[i], k4 = lk4[i];
                As[nb][k4 + 0][m] = pa[i].x; As[nb][k4 + 1][m] = pa[i].y;
                As[nb][k4 + 2][m] = pa[i].z; As[nb][k4 + 3][m] = pa[i].w;
                Bs[nb][k4 + 0][m] = pb[i].x; Bs[nb][k4 + 1][m] = pb[i].y;
                Bs[nb][k4 + 2][m] = pb[i].z; Bs[nb][k4 + 3][m] = pb[i].w;
            }
        }
        __syncthreads();
        cur ^= 1;
    }

#pragma unroll
    for (int i = 0; i < 8; i++) {
        int r = mt * 128 + m0 + i;
        if (r >= M) continue;
        float* cp = Cz + (size_t)r * ldc + nt * 128 + n0;
#pragma unroll
        for (int j = 0; j < 4; j++) {
            float2 v = unpack2(acc[i][j]);
            cp[2 * j] = v.x;
            cp[2 * j + 1] = v.y;
        }
    }
}

// ---------------- reduce split-K partials into emb ----------------
__global__ void reduce_emb_kernel()
{
    int i = blockIdx.x * 256 + threadIdx.x;
    if (i >= TT * EE) return;
    float s = 0.f;
#pragma unroll
    for (int p = 0; p < SPLITS; p++) s += g_part[p * (512 * 512) + i];
    g_emb[i] = s;
}

// ---------------- xproj = emb @ W_x^T + b  (64x64 tiles, K=512) ----------------
__global__ void __launch_bounds__(256)
xproj_kernel(const float* __restrict__ W_x, const float* __restrict__ bias)
{
    __shared__ float As[16][68];
    __shared__ float Bs[16][68];
    const int tid = threadIdx.x;
    const int nt = blockIdx.x, mt = blockIdx.y;
    const int ty = tid >> 4, tx = tid & 15;
    const int m0 = ty * 4, n0 = tx * 4;
    float acc[4][4] = {};

    for (int kb = 0; kb < 512; kb += 16) {
        int m = tid >> 2, k4 = (tid & 3) << 2;
        float4 va = make_float4(0.f, 0.f, 0.f, 0.f);
        int ra = mt * 64 + m;
        if (ra < TT) va = *(const float4*)(g_emb + (size_t)ra * 512 + kb + k4);
        As[k4 + 0][m] = va.x; As[k4 + 1][m] = va.y;
        As[k4 + 2][m] = va.z; As[k4 + 3][m] = va.w;
        float4 vb = *(const float4*)(W_x + (size_t)(nt * 64 + m) * 512 + kb + k4);
        Bs[k4 + 0][m] = vb.x; Bs[k4 + 1][m] = vb.y;
        Bs[k4 + 2][m] = vb.z; Bs[k4 + 3][m] = vb.w;
        __syncthreads();
#pragma unroll
        for (int k = 0; k < 16; k++) {
            float4 a = *(const float4*)&As[k][m0];
            float4 b = *(const float4*)&Bs[k][n0];
            float aa[4] = {a.x, a.y, a.z, a.w};
            float bb[4] = {b.x, b.y, b.z, b.w};
#pragma unroll
            for (int i = 0; i < 4; i++)
#pragma unroll
                for (int j = 0; j < 4; j++) acc[i][j] += aa[i] * bb[j];
        }
        __syncthreads();
    }
#pragma unroll
    for (int i = 0; i < 4; i++) {
        int r = mt * 64 + m0 + i;
        if (r >= TT) continue;
#pragma unroll
        for (int j = 0; j < 4; j++) {
            int col = nt * 64 + n0 + j;
            g_xproj[(size_t)r * 512 + col] = acc[i][j] + bias[col];
        }
    }
}

// ---------------- Elman recurrence: EXACT R1 version (measured 621us) ----------
__global__ void __cluster_dims__(8, 1, 1) __launch_bounds__(1024, 1)
rnn_kernel(const float* __restrict__ W_h)
{
    __shared__ float hbuf[2][512];
    __shared__ float pbuf[64][17];
    const int tid = threadIdx.x;
    const int w = tid >> 5, l = tid & 31;
    const int g = w & 1, s = w >> 1;
    const int c = (int)blockIdx.x;                 // == cluster rank (grid == 1 cluster)
    const int row = c * 64 + g * 32 + l;
    const int kbase = s * 32;

    ulonglong2 wv[8];
    {
        const ulonglong2* wp = (const ulonglong2*)(W_h + (size_t)row * 512 + kbase);
#pragma unroll
        for (int j = 0; j < 8; j++) wv[j] = wp[j];
    }
    for (int i = tid; i < 512; i += 1024) hbuf[0][i] = 0.f;

    uint32_t hbase_local = (uint32_t)__cvta_generic_to_shared(&hbuf[0][0]);
    uint32_t peer[8];
#pragma unroll
    for (int p = 0; p < 8; p++)
        asm("mapa.shared::cluster.u32 %0, %1, %2;" : "=r"(peer[p]) : "r"(hbase_local), "r"(p));

    float xp = (tid < 64) ? g_xproj[(size_t)c * 64 + tid] : 0.f;

    __syncthreads();
    asm volatile("barrier.cluster.arrive.aligned;" ::: "memory");
    asm volatile("barrier.cluster.wait.aligned;" ::: "memory");

    for (int t = 0; t < TT; t++) {
        const int cur = t & 1;
        const ulonglong2* hp = (const ulonglong2*)&hbuf[cur][kbase];
        unsigned long long acc = 0ull;
#pragma unroll
        for (int j = 0; j < 8; j++) {
            ulonglong2 hh = hp[j];
            fma2(acc, wv[j].x, hh.x);
            fma2(acc, wv[j].y, hh.y);
        }
        float2 f = unpack2(acc);
        pbuf[g * 32 + l][s] = f.x + f.y;
        __syncthreads();
        if (tid < 64) {
            float x = xp;
#pragma unroll
            for (int s2 = 0; s2 < 16; s2++) x += pbuf[tid][s2];
            float h = 1.f / (1.f + __expf(-x));
            g_hs[(size_t)t * 512 + c * 64 + tid] = h;
            uint32_t off = (uint32_t)(((cur ^ 1) * 512 + c * 64 + tid) * 4);
#pragma unroll
            for (int p = 0; p < 8; p++)
                asm volatile("st.shared::cluster.f32 [%0], %1;"
                             :: "r"(peer[p] + off), "f"(h) : "memory");
            int tn = (t + 1 < TT) ? (t + 1) : t;
            xp = g_xproj[(size_t)tn * 512 + c * 64 + tid];
        }
        asm volatile("barrier.cluster.arrive.aligned;" ::: "memory");
        asm volatile("barrier.cluster.wait.aligned;" ::: "memory");
    }
}

// ---------------- row softmax over V=32000 ----------------
__global__ void __launch_bounds__(256)
softmax_kernel(float* __restrict__ out)
{
    const int t = blockIdx.x;
    const int tid = threadIdx.x;
    const float4* r4 = (const float4*)(g_logits + (size_t)t * VV);
    float4* o4 = (float4*)(out + (size_t)t * VV);
    __shared__ float red[256];

    float mx = -3.402823466e38f;
    for (int i = tid; i < VV / 4; i += 256) {
        float4 v = r4[i];
        mx = fmaxf(mx, fmaxf(fmaxf(v.x, v.y), fmaxf(v.z, v.w)));
    }
    red[tid] = mx; __syncthreads();
    for (int o = 128; o > 0; o >>= 1) {
        if (tid < o) red[tid] = fmaxf(red[tid], red[tid + o]);
        __syncthreads();
    }
    mx = red[0]; __syncthreads();

    float sum = 0.f;
    for (int i = tid; i < VV / 4; i += 256) {
        float4 v = r4[i];
        v.x = __expf(v.x - mx); v.y = __expf(v.y - mx);
        v.z = __expf(v.z - mx); v.w = __expf(v.w - mx);
        o4[i] = v;
        sum += (v.x + v.y) + (v.z + v.w);
    }
    red[tid] = sum; __syncthreads();
    for (int o = 128; o > 0; o >>= 1) {
        if (tid < o) red[tid] += red[tid + o];
        __syncthreads();
    }
    float inv = 1.f / red[0];

    for (int i = tid; i < VV / 4; i += 256) {
        float4 v = o4[i];
        v.x *= inv; v.y *= inv; v.z *= inv; v.w *= inv;
        o4[i] = v;
    }
}

// ---------------- launch ----------------
extern "C" void kernel_launch(void* const* d_in, const int* in_sizes, int n_in,
                              void* d_out, int out_size)
{
    const float* sent = (const float*)d_in[0];
    const float* W_e  = (const float*)d_in[1];
    const float* W_x  = (const float*)d_in[2];
    const float* W_h  = (const float*)d_in[3];
    const float* W_p  = (const float*)d_in[4];
    const float* b    = (const float*)d_in[5];
    float* out = (float*)d_out;

    float *part, *hs_ptr, *logits;
    cudaGetSymbolAddress((void**)&part,   g_part);
    cudaGetSymbolAddress((void**)&hs_ptr, g_hs);
    cudaGetSymbolAddress((void**)&logits, g_logits);

    // emb partials: sent[0:511] (511x32000) @ W_e^T (32000x512), split-K=25
    gemm_nt128<<<dim3(4, 4, SPLITS), 256>>>(sent, VV, W_e, VV,
                                            part, 512, (size_t)512 * 512, TT, KCHUNK);
    reduce_emb_kernel<<<(TT * EE + 255) / 256, 256>>>();
    // xproj = emb @ W_x^T + b
    xproj_kernel<<<dim3(8, 8), 256>>>(W_x, b);
    // sequential Elman scan (single 8-CTA cluster)
    rnn_kernel<<<8, 1024>>>(W_h);
    // logits = hs @ W_p^T
    gemm_nt128<<<dim3(250, 4, 1), 256>>>(hs_ptr, 512, W_p, 512,
                                         logits, VV, 0, TT, 512);
    // preds = softmax(logits)
    softmax_kernel<<<TT, 256>>>(out);
}

// round 9
// speedup vs baseline: 2.0278x; 1.0717x over previous
#include <cuda_runtime.h>
#include <cuda_bf16.h>
#include <mma.h>
#include <cstdint>
#include <cstddef>

using namespace nvcuda;

#define TT 511          // T-1 rows
#define VV 32000
#define EE 512
#define HH 512
#define SPLITS 25
#define KCHUNK 1280     // 32000 / 25

// ---------------- scratch (__device__ globals; no allocation) ----------------
__device__ float g_part[SPLITS * 512 * 512];
__device__ float g_emb[TT * EE];
__device__ float g_xproj[TT * HH];
__device__ float g_hs[TT * HH];
__device__ float g_logits[(size_t)512 * VV];     // padded to 512 rows for wmma store
__device__ __nv_bfloat16 g_wp_h[(size_t)VV * 512];
__device__ __nv_bfloat16 g_wp_l[(size_t)VV * 512];
__device__ __nv_bfloat16 g_hs_h[512 * 512];      // padded to 512 rows (zeros)
__device__ __nv_bfloat16 g_hs_l[512 * 512];

// ---------------- f32x2 helpers ----------------
__device__ __forceinline__ void fma2(unsigned long long& d, unsigned long long a,
                                     unsigned long long b) {
    asm("fma.rn.f32x2 %0, %1, %2, %0;" : "+l"(d) : "l"(a), "l"(b));
}
__device__ __forceinline__ unsigned long long dup2(float x) {
    unsigned long long d;
    asm("mov.b64 %0, {%1, %1};" : "=l"(d) : "f"(x));
    return d;
}
__device__ __forceinline__ float2 unpack2(unsigned long long d) {
    float2 r;
    asm("mov.b64 {%0, %1}, %2;" : "=f"(r.x), "=f"(r.y) : "l"(d));
    return r;
}

// ---------------- 128x128 NT fp32 GEMM (GEMM1), double-buffered, occ 2 ----------
__global__ void __launch_bounds__(256, 2)
gemm_nt128(const float* __restrict__ A, int lda,
           const float* __restrict__ B, int ldb,
           float* __restrict__ C, int ldc, size_t zStride,
           int M, int kLen)
{
    __shared__ float As[2][16][132];
    __shared__ float Bs[2][16][132];
    const int tid = threadIdx.x;
    const int nt = blockIdx.x, mt = blockIdx.y, sz = blockIdx.z;
    const int kOff = sz * kLen;
    float* Cz = C + (size_t)sz * zStride;
    const int ty = tid >> 4, tx = tid & 15;
    const int m0 = ty * 8, n0 = tx * 8;

    int lm[2], lk4[2], ra[2], rb[2];
    bool aok[2];
#pragma unroll
    for (int i = 0; i < 2; i++) {
        int idx = tid + i * 256;
        lm[i] = idx >> 2;
        lk4[i] = (idx & 3) << 2;
        ra[i] = mt * 128 + lm[i];
        rb[i] = nt * 128 + lm[i];
        aok[i] = (ra[i] < M);
    }

    unsigned long long acc[8][4];
#pragma unroll
    for (int i = 0; i < 8; i++)
#pragma unroll
        for (int j = 0; j < 4; j++) acc[i][j] = 0ull;

#pragma unroll
    for (int i = 0; i < 2; i++) {
        size_t gk = (size_t)(kOff + lk4[i]);
        float4 va = aok[i] ? *(const float4*)(A + (size_t)ra[i] * lda + gk)
                           : make_float4(0.f, 0.f, 0.f, 0.f);
        float4 vb = *(const float4*)(B + (size_t)rb[i] * ldb + gk);
        int m = lm[i], k4 = lk4[i];
        As[0][k4 + 0][m] = va.x; As[0][k4 + 1][m] = va.y;
        As[0][k4 + 2][m] = va.z; As[0][k4 + 3][m] = va.w;
        Bs[0][k4 + 0][m] = vb.x; Bs[0][k4 + 1][m] = vb.y;
        Bs[0][k4 + 2][m] = vb.z; Bs[0][k4 + 3][m] = vb.w;
    }
    __syncthreads();

    int cur = 0;
    for (int kb = 0; kb < kLen; kb += 16) {
        const bool has_next = (kb + 16 < kLen);
        float4 pa[2], pb[2];
        if (has_next) {
#pragma unroll
            for (int i = 0; i < 2; i++) {
                size_t gk = (size_t)(kOff + kb + 16 + lk4[i]);
                pa[i] = aok[i] ? *(const float4*)(A + (size_t)ra[i] * lda + gk)
                               : make_float4(0.f, 0.f, 0.f, 0.f);
                pb[i] = *(const float4*)(B + (size_t)rb[i] * ldb + gk);
            }
        }
#pragma unroll
        for (int k = 0; k < 16; k++) {
            float4 a0 = *(const float4*)&As[cur][k][m0];
            float4 a1 = *(const float4*)&As[cur][k][m0 + 4];
            ulonglong2 b0 = *(const ulonglong2*)&Bs[cur][k][n0];
            ulonglong2 b1 = *(const ulonglong2*)&Bs[cur][k][n0 + 4];
            float av[8] = {a0.x, a0.y, a0.z, a0.w, a1.x, a1.y, a1.z, a1.w};
#pragma unroll
            for (int i = 0; i < 8; i++) {
                unsigned long long ad = dup2(av[i]);
                fma2(acc[i][0], ad, b0.x);
                fma2(acc[i][1], ad, b0.y);
                fma2(acc[i][2], ad, b1.x);
                fma2(acc[i][3], ad, b1.y);
            }
        }
        if (has_next) {
            int nb = cur ^ 1;
#pragma unroll
            for (int i = 0; i < 2; i++) {
                int m = lm[i], k4 = lk4[i];
                As[nb][k4 + 0][m] = pa[i].x; As[nb][k4 + 1][m] = pa[i].y;
                As[nb][k4 + 2][m] = pa[i].z; As[nb][k4 + 3][m] = pa[i].w;
                Bs[nb][k4 + 0][m] = pb[i].x; Bs[nb][k4 + 1][m] = pb[i].y;
                Bs[nb][k4 + 2][m] = pb[i].z; Bs[nb][k4 + 3][m] = pb[i].w;
            }
        }
        __syncthreads();
        cur ^= 1;
    }
#pragma unroll
    for (int i = 0; i < 8; i++) {
        int r = mt * 128 + m0 + i;
        if (r >= M) continue;
        float* cp = Cz + (size_t)r * ldc + nt * 128 + n0;
#pragma unroll
        for (int j = 0; j < 4; j++) {
            float2 v = unpack2(acc[i][j]);
            cp[2 * j] = v.x;
            cp[2 * j + 1] = v.y;
        }
    }
}

// ---------------- reduce split-K partials into emb ----------------
__global__ void reduce_emb_kernel()
{
    int i = blockIdx.x * 256 + threadIdx.x;
    if (i >= TT * EE) return;
    float s = 0.f;
#pragma unroll
    for (int p = 0; p < SPLITS; p++) s += g_part[p * (512 * 512) + i];
    g_emb[i] = s;
}

// ---------------- xproj = emb @ W_x^T + b ----------------
__global__ void __launch_bounds__(256)
xproj_kernel(const float* __restrict__ W_x, const float* __restrict__ bias)
{
    __shared__ float As[16][68];
    __shared__ float Bs[16][68];
    const int tid = threadIdx.x;
    const int nt = blockIdx.x, mt = blockIdx.y;
    const int ty = tid >> 4, tx = tid & 15;
    const int m0 = ty * 4, n0 = tx * 4;
    float acc[4][4] = {};

    for (int kb = 0; kb < 512; kb += 16) {
        int m = tid >> 2, k4 = (tid & 3) << 2;
        float4 va = make_float4(0.f, 0.f, 0.f, 0.f);
        int ra = mt * 64 + m;
        if (ra < TT) va = *(const float4*)(g_emb + (size_t)ra * 512 + kb + k4);
        As[k4 + 0][m] = va.x; As[k4 + 1][m] = va.y;
        As[k4 + 2][m] = va.z; As[k4 + 3][m] = va.w;
        float4 vb = *(const float4*)(W_x + (size_t)(nt * 64 + m) * 512 + kb + k4);
        Bs[k4 + 0][m] = vb.x; Bs[k4 + 1][m] = vb.y;
        Bs[k4 + 2][m] = vb.z; Bs[k4 + 3][m] = vb.w;
        __syncthreads();
#pragma unroll
        for (int k = 0; k < 16; k++) {
            float4 a = *(const float4*)&As[k][m0];
            float4 b = *(const float4*)&Bs[k][n0];
            float aa[4] = {a.x, a.y, a.z, a.w};
            float bb[4] = {b.x, b.y, b.z, b.w};
#pragma unroll
            for (int i = 0; i < 4; i++)
#pragma unroll
                for (int j = 0; j < 4; j++) acc[i][j] += aa[i] * bb[j];
        }
        __syncthreads();
    }
#pragma unroll
    for (int i = 0; i < 4; i++) {
        int r = mt * 64 + m0 + i;
        if (r >= TT) continue;
#pragma unroll
        for (int j = 0; j < 4; j++) {
            int col = nt * 64 + n0 + j;
            g_xproj[(size_t)r * 512 + col] = acc[i][j] + bias[col];
        }
    }
}

// ---------------- Elman recurrence: EXACT R1 version (measured ~621us) ----------
__global__ void __cluster_dims__(8, 1, 1) __launch_bounds__(1024, 1)
rnn_kernel(const float* __restrict__ W_h)
{
    __shared__ float hbuf[2][512];
    __shared__ float pbuf[64][17];
    const int tid = threadIdx.x;
    const int w = tid >> 5, l = tid & 31;
    const int g = w & 1, s = w >> 1;
    const int c = (int)blockIdx.x;
    const int row = c * 64 + g * 32 + l;
    const int kbase = s * 32;

    ulonglong2 wv[8];
    {
        const ulonglong2* wp = (const ulonglong2*)(W_h + (size_t)row * 512 + kbase);
#pragma unroll
        for (int j = 0; j < 8; j++) wv[j] = wp[j];
    }
    for (int i = tid; i < 512; i += 1024) hbuf[0][i] = 0.f;

    uint32_t hbase_local = (uint32_t)__cvta_generic_to_shared(&hbuf[0][0]);
    uint32_t peer[8];
#pragma unroll
    for (int p = 0; p < 8; p++)
        asm("mapa.shared::cluster.u32 %0, %1, %2;" : "=r"(peer[p]) : "r"(hbase_local), "r"(p));

    float xp = (tid < 64) ? g_xproj[(size_t)c * 64 + tid] : 0.f;

    __syncthreads();
    asm volatile("barrier.cluster.arrive.aligned;" ::: "memory");
    asm volatile("barrier.cluster.wait.aligned;" ::: "memory");

    for (int t = 0; t < TT; t++) {
        const int cur = t & 1;
        const ulonglong2* hp = (const ulonglong2*)&hbuf[cur][kbase];
        unsigned long long acc = 0ull;
#pragma unroll
        for (int j = 0; j < 8; j++) {
            ulonglong2 hh = hp[j];
            fma2(acc, wv[j].x, hh.x);
            fma2(acc, wv[j].y, hh.y);
        }
        float2 f = unpack2(acc);
        pbuf[g * 32 + l][s] = f.x + f.y;
        __syncthreads();
        if (tid < 64) {
            float x = xp;
#pragma unroll
            for (int s2 = 0; s2 < 16; s2++) x += pbuf[tid][s2];
            float h = 1.f / (1.f + __expf(-x));
            g_hs[(size_t)t * 512 + c * 64 + tid] = h;
            uint32_t off = (uint32_t)(((cur ^ 1) * 512 + c * 64 + tid) * 4);
#pragma unroll
            for (int p = 0; p < 8; p++)
                asm volatile("st.shared::cluster.f32 [%0], %1;"
                             :: "r"(peer[p] + off), "f"(h) : "memory");
            int tn = (t + 1 < TT) ? (t + 1) : t;
            xp = g_xproj[(size_t)tn * 512 + c * 64 + tid];
        }
        asm volatile("barrier.cluster.arrive.aligned;" ::: "memory");
        asm volatile("barrier.cluster.wait.aligned;" ::: "memory");
    }
}

// ---------------- bf16 hi/lo splits ----------------
__global__ void prep_wp_kernel(const float* __restrict__ W_p)
{
    size_t i = (size_t)blockIdx.x * 1024 + threadIdx.x;
    if (i >= (size_t)VV * 512) return;
    float v = W_p[i];
    __nv_bfloat16 h = __float2bfloat16_rn(v);
    g_wp_h[i] = h;
    g_wp_l[i] = __float2bfloat16_rn(v - __bfloat162float(h));
}
__global__ void prep_hs_kernel()
{
    int i = blockIdx.x * 1024 + threadIdx.x;
    if (i >= 512 * 512) return;
    float v = (i < TT * 512) ? g_hs[i] : 0.f;
    __nv_bfloat16 h = __float2bfloat16_rn(v);
    g_hs_h[i] = h;
    g_hs_l[i] = __float2bfloat16_rn(v - __bfloat162float(h));
}

// ---------------- GEMM2 via WMMA bf16 4-pass: logits = hs @ W_p^T ---------------
// CTA tile 128(M) x 128(N), 8 warps in 2x4 (each 64x32 = 4x2 m16n16k16 frags).
// K chunks of 32; A/B hi+lo tiles in smem ([128][48] bf16: 96B rows, 32B-multiple
// so every load_matrix_sync pointer is 32B-aligned; pad kills bank conflicts).
// Cooperative load: 128 rows x 4 x 16B segments = 512 items / 256 thr = 2 iters.
#define G2_LD 48
__global__ void __launch_bounds__(256, 2)
gemm2_wmma(float* __restrict__ C)
{
    __shared__ __align__(32) __nv_bfloat16 Ah[128][G2_LD], Al[128][G2_LD];
    __shared__ __align__(32) __nv_bfloat16 Bh[128][G2_LD], Bl[128][G2_LD];

    const int tid = threadIdx.x;
    const int wid = tid >> 5;
    const int warp_m = wid >> 2;          // 0..1
    const int warp_n = wid & 3;           // 0..3
    const int nt = blockIdx.x, mt = blockIdx.y;
    const int arow = mt * 128, brow = nt * 128;

    wmma::fragment<wmma::accumulator, 16, 16, 16, float> acc[4][2];
#pragma unroll
    for (int mi = 0; mi < 4; mi++)
#pragma unroll
        for (int ni = 0; ni < 2; ni++) wmma::fill_fragment(acc[mi][ni], 0.f);

    for (int kc = 0; kc < 512; kc += 32) {
        // cooperative loads: 512 (row, 16B-seg) items over 256 threads = 2 iters
#pragma unroll
        for (int i = 0; i < 2; i++) {
            int lin = tid + i * 256;
            int r = lin >> 2, seg = lin & 3;
            *(uint4*)&Ah[r][seg * 8] = *(const uint4*)(g_hs_h + (size_t)(arow + r) * 512 + kc + seg * 8);
            *(uint4*)&Al[r][seg * 8] = *(const uint4*)(g_hs_l + (size_t)(arow + r) * 512 + kc + seg * 8);
            *(uint4*)&Bh[r][seg * 8] = *(const uint4*)(g_wp_h + (size_t)(brow + r) * 512 + kc + seg * 8);
            *(uint4*)&Bl[r][seg * 8] = *(const uint4*)(g_wp_l + (size_t)(brow + r) * 512 + kc + seg * 8);
        }
        __syncthreads();

#pragma unroll
        for (int kk = 0; kk < 2; kk++) {
            const int k0 = kk * 16;
            wmma::fragment<wmma::matrix_a, 16, 16, 16, __nv_bfloat16, wmma::row_major> ah[4], al[4];
            wmma::fragment<wmma::matrix_b, 16, 16, 16, __nv_bfloat16, wmma::col_major> bh[2], bl[2];
#pragma unroll
            for (int mi = 0; mi < 4; mi++) {
                wmma::load_matrix_sync(ah[mi], &Ah[warp_m * 64 + mi * 16][k0], G2_LD);
                wmma::load_matrix_sync(al[mi], &Al[warp_m * 64 + mi * 16][k0], G2_LD);
            }
#pragma unroll
            for (int ni = 0; ni < 2; ni++) {
                wmma::load_matrix_sync(bh[ni], &Bh[warp_n * 32 + ni * 16][k0], G2_LD);
                wmma::load_matrix_sync(bl[ni], &Bl[warp_n * 32 + ni * 16][k0], G2_LD);
            }
#pragma unroll
            for (int mi = 0; mi < 4; mi++)
#pragma unroll
                for (int ni = 0; ni < 2; ni++) {
                    wmma::mma_sync(acc[mi][ni], ah[mi], bh[ni], acc[mi][ni]);
                    wmma::mma_sync(acc[mi][ni], ah[mi], bl[ni], acc[mi][ni]);
                    wmma::mma_sync(acc[mi][ni], al[mi], bh[ni], acc[mi][ni]);
                    wmma::mma_sync(acc[mi][ni], al[mi], bl[ni], acc[mi][ni]);
                }
        }
        __syncthreads();
    }

#pragma unroll
    for (int mi = 0; mi < 4; mi++)
#pragma unroll
        for (int ni = 0; ni < 2; ni++) {
            int m = arow + warp_m * 64 + mi * 16;
            int n = brow + warp_n * 32 + ni * 16;
            wmma::store_matrix_sync(C + (size_t)m * VV + n, acc[mi][ni], VV,
                                    wmma::mem_row_major);
        }
}

// ---------------- fused single-pass row softmax over V=32000 ----------------
__global__ void __launch_bounds__(512)
softmax_kernel(float* __restrict__ out)
{
    extern __shared__ float buf[];                     // 32000 floats
    __shared__ float red[512];
    const int t = blockIdx.x;
    const int tid = threadIdx.x;
    const float4* r4 = (const float4*)(g_logits + (size_t)t * VV);
    float4* b4 = (float4*)buf;
    float4* o4 = (float4*)(out + (size_t)t * VV);

    float mx = -3.402823466e38f;
    for (int i = tid; i < VV / 4; i += 512) {
        float4 v = r4[i];
        b4[i] = v;
        mx = fmaxf(mx, fmaxf(fmaxf(v.x, v.y), fmaxf(v.z, v.w)));
    }
    red[tid] = mx; __syncthreads();
    for (int o = 256; o > 0; o >>= 1) {
        if (tid < o) red[tid] = fmaxf(red[tid], red[tid + o]);
        __syncthreads();
    }
    mx = red[0]; __syncthreads();

    float sum = 0.f;
    for (int i = tid; i < VV / 4; i += 512) {
        float4 v = b4[i];
        v.x = __expf(v.x - mx); v.y = __expf(v.y - mx);
        v.z = __expf(v.z - mx); v.w = __expf(v.w - mx);
        b4[i] = v;
        sum += (v.x + v.y) + (v.z + v.w);
    }
    red[tid] = sum; __syncthreads();
    for (int o = 256; o > 0; o >>= 1) {
        if (tid < o) red[tid] += red[tid + o];
        __syncthreads();
    }
    float inv = 1.f / red[0];

    for (int i = tid; i < VV / 4; i += 512) {
        float4 v = b4[i];
        v.x *= inv; v.y *= inv; v.z *= inv; v.w *= inv;
        o4[i] = v;
    }
}

// ---------------- launch ----------------
extern "C" void kernel_launch(void* const* d_in, const int* in_sizes, int n_in,
                              void* d_out, int out_size)
{
    const float* sent = (const float*)d_in[0];
    const float* W_e  = (const float*)d_in[1];
    const float* W_x  = (const float*)d_in[2];
    const float* W_h  = (const float*)d_in[3];
    const float* W_p  = (const float*)d_in[4];
    const float* b    = (const float*)d_in[5];
    float* out = (float*)d_out;

    float *part, *logits;
    cudaGetSymbolAddress((void**)&part,   g_part);
    cudaGetSymbolAddress((void**)&logits, g_logits);

    cudaFuncSetAttribute(softmax_kernel,
                         cudaFuncAttributeMaxDynamicSharedMemorySize, VV * 4);

    // W_p hi/lo split (independent of everything else)
    prep_wp_kernel<<<(VV * 512 + 1023) / 1024, 1024>>>(W_p);
    // emb partials: sent[0:511] @ W_e^T, split-K=25
    gemm_nt128<<<dim3(4, 4, SPLITS), 256>>>(sent, VV, W_e, VV,
                                            part, 512, (size_t)512 * 512, TT, KCHUNK);
    reduce_emb_kernel<<<(TT * EE + 255) / 256, 256>>>();
    xproj_kernel<<<dim3(8, 8), 256>>>(W_x, b);
    rnn_kernel<<<8, 1024>>>(W_h);
    prep_hs_kernel<<<(512 * 512 + 1023) / 1024, 1024>>>();
    // logits = hs @ W_p^T on tensor cores (WMMA bf16 4-pass)
    gemm2_wmma<<<dim3(250, 4), 256>>>(logits);
    softmax_kernel<<<TT, 512, VV * 4>>>(out);
}

// round 10
// speedup vs baseline: 2.0604x; 1.0161x over previous
#include <cuda_runtime.h>
#include <cuda_bf16.h>
#include <mma.h>
#include <cstdint>
#include <cstddef>

using namespace nvcuda;

#define TT 511          // T-1 rows
#define VV 32000
#define EE 512
#define HH 512
#define SPLITS 25
#define KCHUNK 1280     // 32000 / 25

// ---------------- scratch (__device__ globals; no allocation) ----------------
__device__ float g_part[SPLITS * 512 * 512];
__device__ float g_emb[TT * EE];
__device__ float g_xproj[TT * HH];
__device__ float g_hs[TT * HH];
__device__ float g_logits[(size_t)512 * VV];     // padded to 512 rows for wmma store
__device__ __nv_bfloat16 g_wp_h[(size_t)VV * 512];
__device__ __nv_bfloat16 g_wp_l[(size_t)VV * 512];
__device__ __nv_bfloat16 g_hs_h[512 * 512];      // padded to 512 rows (zeros)
__device__ __nv_bfloat16 g_hs_l[512 * 512];

// ---------------- f32x2 helpers ----------------
__device__ __forceinline__ void fma2(unsigned long long& d, unsigned long long a,
                                     unsigned long long b) {
    asm("fma.rn.f32x2 %0, %1, %2, %0;" : "+l"(d) : "l"(a), "l"(b));
}
__device__ __forceinline__ unsigned long long dup2(float x) {
    unsigned long long d;
    asm("mov.b64 %0, {%1, %1};" : "=l"(d) : "f"(x));
    return d;
}
__device__ __forceinline__ float2 unpack2(unsigned long long d) {
    float2 r;
    asm("mov.b64 {%0, %1}, %2;" : "=f"(r.x), "=f"(r.y) : "l"(d));
    return r;
}

// ---------------- 128x128 NT fp32 GEMM (GEMM1), double-buffered, occ 2 ----------
__global__ void __launch_bounds__(256, 2)
gemm_nt128(const float* __restrict__ A, int lda,
           const float* __restrict__ B, int ldb,
           float* __restrict__ C, int ldc, size_t zStride,
           int M, int kLen)
{
    __shared__ float As[2][16][132];
    __shared__ float Bs[2][16][132];
    const int tid = threadIdx.x;
    const int nt = blockIdx.x, mt = blockIdx.y, sz = blockIdx.z;
    const int kOff = sz * kLen;
    float* Cz = C + (size_t)sz * zStride;
    const int ty = tid >> 4, tx = tid & 15;
    const int m0 = ty * 8, n0 = tx * 8;

    int lm[2], lk4[2], ra[2], rb[2];
    bool aok[2];
#pragma unroll
    for (int i = 0; i < 2; i++) {
        int idx = tid + i * 256;
        lm[i] = idx >> 2;
        lk4[i] = (idx & 3) << 2;
        ra[i] = mt * 128 + lm[i];
        rb[i] = nt * 128 + lm[i];
        aok[i] = (ra[i] < M);
    }

    unsigned long long acc[8][4];
#pragma unroll
    for (int i = 0; i < 8; i++)
#pragma unroll
        for (int j = 0; j < 4; j++) acc[i][j] = 0ull;

#pragma unroll
    for (int i = 0; i < 2; i++) {
        size_t gk = (size_t)(kOff + lk4[i]);
        float4 va = aok[i] ? *(const float4*)(A + (size_t)ra[i] * lda + gk)
                           : make_float4(0.f, 0.f, 0.f, 0.f);
        float4 vb = *(const float4*)(B + (size_t)rb[i] * ldb + gk);
        int m = lm[i], k4 = lk4[i];
        As[0][k4 + 0][m] = va.x; As[0][k4 + 1][m] = va.y;
        As[0][k4 + 2][m] = va.z; As[0][k4 + 3][m] = va.w;
        Bs[0][k4 + 0][m] = vb.x; Bs[0][k4 + 1][m] = vb.y;
        Bs[0][k4 + 2][m] = vb.z; Bs[0][k4 + 3][m] = vb.w;
    }
    __syncthreads();

    int cur = 0;
    for (int kb = 0; kb < kLen; kb += 16) {
        const bool has_next = (kb + 16 < kLen);
        float4 pa[2], pb[2];
        if (has_next) {
#pragma unroll
            for (int i = 0; i < 2; i++) {
                size_t gk = (size_t)(kOff + kb + 16 + lk4[i]);
                pa[i] = aok[i] ? *(const float4*)(A + (size_t)ra[i] * lda + gk)
                               : make_float4(0.f, 0.f, 0.f, 0.f);
                pb[i] = *(const float4*)(B + (size_t)rb[i] * ldb + gk);
            }
        }
#pragma unroll
        for (int k = 0; k < 16; k++) {
            float4 a0 = *(const float4*)&As[cur][k][m0];
            float4 a1 = *(const float4*)&As[cur][k][m0 + 4];
            ulonglong2 b0 = *(const ulonglong2*)&Bs[cur][k][n0];
            ulonglong2 b1 = *(const ulonglong2*)&Bs[cur][k][n0 + 4];
            float av[8] = {a0.x, a0.y, a0.z, a0.w, a1.x, a1.y, a1.z, a1.w};
#pragma unroll
            for (int i = 0; i < 8; i++) {
                unsigned long long ad = dup2(av[i]);
                fma2(acc[i][0], ad, b0.x);
                fma2(acc[i][1], ad, b0.y);
                fma2(acc[i][2], ad, b1.x);
                fma2(acc[i][3], ad, b1.y);
            }
        }
        if (has_next) {
            int nb = cur ^ 1;
#pragma unroll
            for (int i = 0; i < 2; i++) {
                int m = lm[i], k4 = lk4[i];
                As[nb][k4 + 0][m] = pa[i].x; As[nb][k4 + 1][m] = pa[i].y;
                As[nb][k4 + 2][m] = pa[i].z; As[nb][k4 + 3][m] = pa[i].w;
                Bs[nb][k4 + 0][m] = pb[i].x; Bs[nb][k4 + 1][m] = pb[i].y;
                Bs[nb][k4 + 2][m] = pb[i].z; Bs[nb][k4 + 3][m] = pb[i].w;
            }
        }
        __syncthreads();
        cur ^= 1;
    }
#pragma unroll
    for (int i = 0; i < 8; i++) {
        int r = mt * 128 + m0 + i;
        if (r >= M) continue;
        float* cp = Cz + (size_t)r * ldc + nt * 128 + n0;
#pragma unroll
        for (int j = 0; j < 4; j++) {
            float2 v = unpack2(acc[i][j]);
            cp[2 * j] = v.x;
            cp[2 * j + 1] = v.y;
        }
    }
}

// ---------------- reduce split-K partials into emb ----------------
__global__ void reduce_emb_kernel()
{
    int i = blockIdx.x * 256 + threadIdx.x;
    if (i >= TT * EE) return;
    float s = 0.f;
#pragma unroll
    for (int p = 0; p < SPLITS; p++) s += g_part[p * (512 * 512) + i];
    g_emb[i] = s;
}

// ---------------- xproj = emb @ W_x^T + b ----------------
__global__ void __launch_bounds__(256)
xproj_kernel(const float* __restrict__ W_x, const float* __restrict__ bias)
{
    __shared__ float As[16][68];
    __shared__ float Bs[16][68];
    const int tid = threadIdx.x;
    const int nt = blockIdx.x, mt = blockIdx.y;
    const int ty = tid >> 4, tx = tid & 15;
    const int m0 = ty * 4, n0 = tx * 4;
    float acc[4][4] = {};

    for (int kb = 0; kb < 512; kb += 16) {
        int m = tid >> 2, k4 = (tid & 3) << 2;
        float4 va = make_float4(0.f, 0.f, 0.f, 0.f);
        int ra = mt * 64 + m;
        if (ra < TT) va = *(const float4*)(g_emb + (size_t)ra * 512 + kb + k4);
        As[k4 + 0][m] = va.x; As[k4 + 1][m] = va.y;
        As[k4 + 2][m] = va.z; As[k4 + 3][m] = va.w;
        float4 vb = *(const float4*)(W_x + (size_t)(nt * 64 + m) * 512 + kb + k4);
        Bs[k4 + 0][m] = vb.x; Bs[k4 + 1][m] = vb.y;
        Bs[k4 + 2][m] = vb.z; Bs[k4 + 3][m] = vb.w;
        __syncthreads();
#pragma unroll
        for (int k = 0; k < 16; k++) {
            float4 a = *(const float4*)&As[k][m0];
            float4 b = *(const float4*)&Bs[k][n0];
            float aa[4] = {a.x, a.y, a.z, a.w};
            float bb[4] = {b.x, b.y, b.z, b.w};
#pragma unroll
            for (int i = 0; i < 4; i++)
#pragma unroll
                for (int j = 0; j < 4; j++) acc[i][j] += aa[i] * bb[j];
        }
        __syncthreads();
    }
#pragma unroll
    for (int i = 0; i < 4; i++) {
        int r = mt * 64 + m0 + i;
        if (r >= TT) continue;
#pragma unroll
        for (int j = 0; j < 4; j++) {
            int col = nt * 64 + n0 + j;
            g_xproj[(size_t)r * 512 + col] = acc[i][j] + bias[col];
        }
    }
}

// ---------------- Elman recurrence: EXACT R1 version (measured ~621us) ----------
__global__ void __cluster_dims__(8, 1, 1) __launch_bounds__(1024, 1)
rnn_kernel(const float* __restrict__ W_h)
{
    __shared__ float hbuf[2][512];
    __shared__ float pbuf[64][17];
    const int tid = threadIdx.x;
    const int w = tid >> 5, l = tid & 31;
    const int g = w & 1, s = w >> 1;
    const int c = (int)blockIdx.x;
    const int row = c * 64 + g * 32 + l;
    const int kbase = s * 32;

    ulonglong2 wv[8];
    {
        const ulonglong2* wp = (const ulonglong2*)(W_h + (size_t)row * 512 + kbase);
#pragma unroll
        for (int j = 0; j < 8; j++) wv[j] = wp[j];
    }
    for (int i = tid; i < 512; i += 1024) hbuf[0][i] = 0.f;

    uint32_t hbase_local = (uint32_t)__cvta_generic_to_shared(&hbuf[0][0]);
    uint32_t peer[8];
#pragma unroll
    for (int p = 0; p < 8; p++)
        asm("mapa.shared::cluster.u32 %0, %1, %2;" : "=r"(peer[p]) : "r"(hbase_local), "r"(p));

    float xp = (tid < 64) ? g_xproj[(size_t)c * 64 + tid] : 0.f;

    __syncthreads();
    asm volatile("barrier.cluster.arrive.aligned;" ::: "memory");
    asm volatile("barrier.cluster.wait.aligned;" ::: "memory");

    for (int t = 0; t < TT; t++) {
        const int cur = t & 1;
        const ulonglong2* hp = (const ulonglong2*)&hbuf[cur][kbase];
        unsigned long long acc = 0ull;
#pragma unroll
        for (int j = 0; j < 8; j++) {
            ulonglong2 hh = hp[j];
            fma2(acc, wv[j].x, hh.x);
            fma2(acc, wv[j].y, hh.y);
        }
        float2 f = unpack2(acc);
        pbuf[g * 32 + l][s] = f.x + f.y;
        __syncthreads();
        if (tid < 64) {
            float x = xp;
#pragma unroll
            for (int s2 = 0; s2 < 16; s2++) x += pbuf[tid][s2];
            float h = 1.f / (1.f + __expf(-x));
            g_hs[(size_t)t * 512 + c * 64 + tid] = h;
            uint32_t off = (uint32_t)(((cur ^ 1) * 512 + c * 64 + tid) * 4);
#pragma unroll
            for (int p = 0; p < 8; p++)
                asm volatile("st.shared::cluster.f32 [%0], %1;"
                             :: "r"(peer[p] + off), "f"(h) : "memory");
            int tn = (t + 1 < TT) ? (t + 1) : t;
            xp = g_xproj[(size_t)tn * 512 + c * 64 + tid];
        }
        asm volatile("barrier.cluster.arrive.aligned;" ::: "memory");
        asm volatile("barrier.cluster.wait.aligned;" ::: "memory");
    }
}

// ---------------- bf16 hi/lo splits ----------------
__global__ void prep_wp_kernel(const float* __restrict__ W_p)
{
    size_t i = (size_t)blockIdx.x * 1024 + threadIdx.x;
    if (i >= (size_t)VV * 512) return;
    float v = W_p[i];
    __nv_bfloat16 h = __float2bfloat16_rn(v);
    g_wp_h[i] = h;
    g_wp_l[i] = __float2bfloat16_rn(v - __bfloat162float(h));
}
__global__ void prep_hs_kernel()
{
    int i = blockIdx.x * 1024 + threadIdx.x;
    if (i >= 512 * 512) return;
    float v = (i < TT * 512) ? g_hs[i] : 0.f;
    __nv_bfloat16 h = __float2bfloat16_rn(v);
    g_hs_h[i] = h;
    g_hs_l[i] = __float2bfloat16_rn(v - __bfloat162float(h));
}

// ---------------- GEMM2 via WMMA bf16 3-pass: logits = hs @ W_p^T ---------------
// CTA tile 128(M) x 256(N), 8 warps in 2x4, warp tile 64x64 (4x4 acc frags).
// 3 passes (hh, hl, lh): the ll term is <= 2^-18 |ab| -> ~5e-6 rel on logits.
// Dynamic smem: Ah/Al [128][48] + Bh/Bl [256][48] bf16 = 73728 B, k-chunk 32.
// Rows are 96 B (32B multiple) so every load_matrix_sync pointer is 32B-aligned.
#define G2_LD 48
#define G2_A_SZ (128 * G2_LD)
#define G2_B_SZ (256 * G2_LD)
#define G2_SMEM ((2 * G2_A_SZ + 2 * G2_B_SZ) * 2)   // 73728 bytes

__global__ void __launch_bounds__(256, 1)
gemm2_wmma(float* __restrict__ C)
{
    extern __shared__ __align__(32) __nv_bfloat16 sm2[];
    __nv_bfloat16* Asm[2] = { sm2, sm2 + G2_A_SZ };                    // hi, lo
    __nv_bfloat16* Bsm[2] = { sm2 + 2 * G2_A_SZ, sm2 + 2 * G2_A_SZ + G2_B_SZ };
    const __nv_bfloat16* Agm[2] = { g_hs_h, g_hs_l };
    const __nv_bfloat16* Bgm[2] = { g_wp_h, g_wp_l };

    const int tid = threadIdx.x;
    const int wid = tid >> 5;
    const int warp_m = wid >> 2;          // 0..1
    const int warp_n = wid & 3;           // 0..3
    const int nt = blockIdx.x, mt = blockIdx.y;
    const int arow = mt * 128, brow = nt * 256;

    wmma::fragment<wmma::accumulator, 16, 16, 16, float> acc[4][4];
#pragma unroll
    for (int mi = 0; mi < 4; mi++)
#pragma unroll
        for (int ni = 0; ni < 4; ni++) wmma::fill_fragment(acc[mi][ni], 0.f);

    for (int kc = 0; kc < 512; kc += 32) {
        // A: 2 splits x 128 rows x 4 x 16B segs = 1024 items / 256 thr = 4 iters
#pragma unroll
        for (int i = 0; i < 4; i++) {
            int lin = tid + i * 256;
            int s = lin >> 9, rem = lin & 511;
            int r = rem >> 2, seg = rem & 3;
            *(uint4*)&Asm[s][r * G2_LD + seg * 8] =
                *(const uint4*)(Agm[s] + (size_t)(arow + r) * 512 + kc + seg * 8);
        }
        // B: 2 splits x 256 rows x 4 segs = 2048 items / 256 thr = 8 iters
#pragma unroll
        for (int i = 0; i < 8; i++) {
            int lin = tid + i * 256;
            int s = lin >> 10, rem = lin & 1023;
            int r = rem >> 2, seg = rem & 3;
            *(uint4*)&Bsm[s][r * G2_LD + seg * 8] =
                *(const uint4*)(Bgm[s] + (size_t)(brow + r) * 512 + kc + seg * 8);
        }
        __syncthreads();

#pragma unroll
        for (int kk = 0; kk < 2; kk++) {
            const int k0 = kk * 16;
            // 3 passes: (a_hi,b_hi), (a_hi,b_lo), (a_lo,b_hi)
#pragma unroll
            for (int p = 0; p < 3; p++) {
                const int pa = (p == 2) ? 1 : 0;
                const int pb = (p == 1) ? 1 : 0;
                wmma::fragment<wmma::matrix_a, 16, 16, 16, __nv_bfloat16, wmma::row_major> af[4];
                wmma::fragment<wmma::matrix_b, 16, 16, 16, __nv_bfloat16, wmma::col_major> bf[4];
#pragma unroll
                for (int mi = 0; mi < 4; mi++)
                    wmma::load_matrix_sync(af[mi],
                        &Asm[pa][(warp_m * 64 + mi * 16) * G2_LD + k0], G2_LD);
#pragma unroll
                for (int ni = 0; ni < 4; ni++)
                    wmma::load_matrix_sync(bf[ni],
                        &Bsm[pb][(warp_n * 64 + ni * 16) * G2_LD + k0], G2_LD);
#pragma unroll
                for (int mi = 0; mi < 4; mi++)
#pragma unroll
                    for (int ni = 0; ni < 4; ni++)
                        wmma::mma_sync(acc[mi][ni], af[mi], bf[ni], acc[mi][ni]);
            }
        }
        __syncthreads();
    }

#pragma unroll
    for (int mi = 0; mi < 4; mi++)
#pragma unroll
        for (int ni = 0; ni < 4; ni++) {
            int m = arow + warp_m * 64 + mi * 16;           // < 512 (C padded)
            int n = brow + warp_n * 64 + ni * 16;           // < 32000
            wmma::store_matrix_sync(C + (size_t)m * VV + n, acc[mi][ni], VV,
                                    wmma::mem_row_major);
        }
}

// ---------------- fused single-pass row softmax over V=32000 ----------------
__global__ void __launch_bounds__(512)
softmax_kernel(float* __restrict__ out)
{
    extern __shared__ float buf[];                     // 32000 floats
    __shared__ float red[512];
    const int t = blockIdx.x;
    const int tid = threadIdx.x;
    const float4* r4 = (const float4*)(g_logits + (size_t)t * VV);
    float4* b4 = (float4*)buf;
    float4* o4 = (float4*)(out + (size_t)t * VV);

    float mx = -3.402823466e38f;
    for (int i = tid; i < VV / 4; i += 512) {
        float4 v = r4[i];
        b4[i] = v;
        mx = fmaxf(mx, fmaxf(fmaxf(v.x, v.y), fmaxf(v.z, v.w)));
    }
    red[tid] = mx; __syncthreads();
    for (int o = 256; o > 0; o >>= 1) {
        if (tid < o) red[tid] = fmaxf(red[tid], red[tid + o]);
        __syncthreads();
    }
    mx = red[0]; __syncthreads();

    float sum = 0.f;
    for (int i = tid; i < VV / 4; i += 512) {
        float4 v = b4[i];
        v.x = __expf(v.x - mx); v.y = __expf(v.y - mx);
        v.z = __expf(v.z - mx); v.w = __expf(v.w - mx);
        b4[i] = v;
        sum += (v.x + v.y) + (v.z + v.w);
    }
    red[tid] = sum; __syncthreads();
    for (int o = 256; o > 0; o >>= 1) {
        if (tid < o) red[tid] += red[tid + o];
        __syncthreads();
    }
    float inv = 1.f / red[0];

    for (int i = tid; i < VV / 4; i += 512) {
        float4 v = b4[i];
        v.x *= inv; v.y *= inv; v.z *= inv; v.w *= inv;
        o4[i] = v;
    }
}

// ---------------- launch ----------------
extern "C" void kernel_launch(void* const* d_in, const int* in_sizes, int n_in,
                              void* d_out, int out_size)
{
    const float* sent = (const float*)d_in[0];
    const float* W_e  = (const float*)d_in[1];
    const float* W_x  = (const float*)d_in[2];
    const float* W_h  = (const float*)d_in[3];
    const float* W_p  = (const float*)d_in[4];
    const float* b    = (const float*)d_in[5];
    float* out = (float*)d_out;

    float *part, *logits;
    cudaGetSymbolAddress((void**)&part,   g_part);
    cudaGetSymbolAddress((void**)&logits, g_logits);

    cudaFuncSetAttribute(softmax_kernel,
                         cudaFuncAttributeMaxDynamicSharedMemorySize, VV * 4);
    cudaFuncSetAttribute(gemm2_wmma,
                         cudaFuncAttributeMaxDynamicSharedMemorySize, G2_SMEM);

    // W_p hi/lo split (independent of everything else)
    prep_wp_kernel<<<(VV * 512 + 1023) / 1024, 1024>>>(W_p);
    // emb partials: sent[0:511] @ W_e^T, split-K=25
    gemm_nt128<<<dim3(4, 4, SPLITS), 256>>>(sent, VV, W_e, VV,
                                            part, 512, (size_t)512 * 512, TT, KCHUNK);
    reduce_emb_kernel<<<(TT * EE + 255) / 256, 256>>>();
    xproj_kernel<<<dim3(8, 8), 256>>>(W_x, b);
    rnn_kernel<<<8, 1024>>>(W_h);
    prep_hs_kernel<<<(512 * 512 + 1023) / 1024, 1024>>>();
    // logits = hs @ W_p^T on tensor cores (WMMA bf16 3-pass, 64x64 warp tiles)
    gemm2_wmma<<<dim3(125, 4), 256, G2_SMEM>>>(logits);
    softmax_kernel<<<TT, 512, VV * 4>>>(out);
}